// round 10
// baseline (speedup 1.0000x reference)
#include <cuda_runtime.h>
#include <cstdint>

#define NVEC 65536
#define DIM  256
#define KCB  4096
#define LOSS_BLOCKS 4096
#define CAND_MAX 40
#define TH 1.0e-3f
#define NTILES 512
#define GRID_MMA 296

__device__ float    g_x2[NVEC];
__device__ float    g_e2[KCB];
__device__ int      g_idx[NVEC];
__device__ double   g_part[LOSS_BLOCKS];
__device__ uint32_t g_bperm[KCB * DIM / 2];   // bf16x2 fragment-permuted codebook
__device__ int      g_fb_rows[NVEC];
__device__ int      g_fb_count;
__device__ unsigned g_tile_ctr;

__device__ __forceinline__ unsigned fenc(float f) {
    unsigned u = __float_as_uint(f);
    return (u & 0x80000000u) ? ~u : (u | 0x80000000u);
}
__device__ __forceinline__ float fdec(unsigned e) {
    unsigned u = (e & 0x80000000u) ? (e ^ 0x80000000u) : ~e;
    return __uint_as_float(u);
}
// pack bf16x2: lo half = v0, hi half = v1
__device__ __forceinline__ uint32_t bfpack(float v0, float v1) {
    uint32_t r;
    asm("cvt.rn.bf16x2.f32 %0, %1, %2;" : "=r"(r) : "f"(v1), "f"(v0));
    return r;
}

// Exact fp32 distance — identical recipe to rounds 1/4/5/7 (rel_err 0.0)
__device__ __forceinline__ float exact_dist(const float* __restrict__ xr,
                                            const float* __restrict__ cr,
                                            float x2, float e2) {
    const float4* x4 = reinterpret_cast<const float4*>(xr);
    const float4* c4 = reinterpret_cast<const float4*>(cr);
    float acc = 0.f;
    #pragma unroll 8
    for (int q = 0; q < 64; q++) {
        float4 a = x4[q], b = c4[q];
        acc = fmaf(a.x, b.x, acc);
        acc = fmaf(a.y, b.y, acc);
        acc = fmaf(a.z, b.z, acc);
        acc = fmaf(a.w, b.w, acc);
    }
    float t = x2 + e2;
    return t - 2.0f * acc;
}

// ---------------------------------------------------------------------------
__global__ void rownorm_kernel(const float* __restrict__ v, int rows, int which) {
    if (which == 0 && blockIdx.x == 0 && threadIdx.x == 0) {
        g_fb_count = 0;
        g_tile_ctr = 0;
    }
    int row  = blockIdx.x * (blockDim.x >> 5) + (threadIdx.x >> 5);
    int lane = threadIdx.x & 31;
    if (row >= rows) return;
    const float4* p = reinterpret_cast<const float4*>(v + (size_t)row * DIM);
    float4 a = p[lane];
    float4 b = p[lane + 32];
    float s = ((a.x * a.x + a.y * a.y) + (a.z * a.z + a.w * a.w))
            + ((b.x * b.x + b.y * b.y) + (b.z * b.z + b.w * b.w));
    #pragma unroll
    for (int off = 16; off; off >>= 1)
        s += __shfl_xor_sync(0xffffffffu, s, off);
    if (lane == 0) {
        if (which) g_e2[row] = s;
        else       g_x2[row] = s;
    }
}

// ---------------------------------------------------------------------------
// Pre-convert codebook to bf16 in mma.m16n8k16 B-fragment layout.
// Layout: [chunk 128][kb 4][nb 16][lane 32][reg 2] (u32 = bf16x2)
//   chunk = kt*4 + dc covers codes kt*128.. and d = dc*64..dc*64+63
//   code = kt*128 + nb*8 + (lane>>2)
//   d0   = dc*64 + kb*16 + 2*(lane&3) + reg*8   (pair d0, d0+1)
// ---------------------------------------------------------------------------
__global__ void bperm_kernel(const float* __restrict__ cb) {
    int o = blockIdx.x * 256 + threadIdx.x;    // total 524288
    int reg = o & 1, lane = (o >> 1) & 31, nb = (o >> 6) & 15, kb = (o >> 10) & 3;
    int chunk = o >> 12, kt = chunk >> 2, dc = chunk & 3;
    int gg = lane >> 2, tig = lane & 3;
    int code = kt * 128 + nb * 8 + gg;
    int d0 = dc * 64 + kb * 16 + 2 * tig + reg * 8;
    const float* r = cb + (size_t)code * DIM;
    g_bperm[o] = bfpack(r[d0], r[d0 + 1]);
}

// ---------------------------------------------------------------------------
// bf16 mma.sync distance GEMM + candidate collection + exact fp32 rescore.
// PERSISTENT work-stealing: 296 CTAs pull 128-row tiles off an atomic counter.
// Per tile: 128 rows x 4096 codes; 8 warps (2 wr x 4 wc); warp tile 64x32.
// ---------------------------------------------------------------------------
#define MMA16(ac, av, bv) \
    asm volatile("mma.sync.aligned.m16n8k16.row.col.f32.bf16.bf16.f32 " \
        "{%0,%1,%2,%3},{%4,%5,%6,%7},{%8,%9},{%0,%1,%2,%3};" \
        : "+f"((ac)[0]), "+f"((ac)[1]), "+f"((ac)[2]), "+f"((ac)[3]) \
        : "r"((av).x), "r"((av).y), "r"((av).z), "r"((av).w), \
          "r"((bv).x), "r"((bv).y))

// chunk = 16KB: 256 threads x 16B x 4
#define LOAD_CHUNK(c, buf) do {                                               \
    const uint32_t* _src = g_bperm + (size_t)(c) * 4096 + tid * 4;            \
    uint32_t _dst = bsb + (uint32_t)(buf) * 16384u + (uint32_t)tid * 16u;     \
    _Pragma("unroll")                                                         \
    for (int _j = 0; _j < 4; _j++)                                            \
        asm volatile("cp.async.cg.shared.global [%0], [%1], 16;"              \
                     :: "r"(_dst + _j * 4096u), "l"(_src + _j * 1024) : "memory"); \
    asm volatile("cp.async.commit_group;" ::: "memory");                      \
} while (0)

__global__ __launch_bounds__(256, 2)
void vq_mma_kernel(const float* __restrict__ x, const float* __restrict__ cb) {
    extern __shared__ uint32_t dsm[];
    uint32_t* As = dsm;            // 16384 u32 = 64KB  (A bf16 fragments)
    uint32_t* Bs = dsm + 16384;    //  8192 u32 = 32KB  (2 x 16KB B chunks)
    __shared__ float x2s[128];
    __shared__ unsigned rmin[128];
    __shared__ int scnt[128];
    __shared__ unsigned short cand[128 * CAND_MAX];
    __shared__ unsigned long long red[128];
    __shared__ int s_tile;

    const int tid = threadIdx.x, lane = tid & 31, warp = tid >> 5;
    const int wr = warp >> 2, wc = warp & 3;
    const int gg = lane >> 2, tig = lane & 3;

    uint32_t bsb;
    asm("{ .reg .u64 t; cvta.to.shared.u64 t, %1; cvt.u32.u64 %0, t; }"
        : "=r"(bsb) : "l"(Bs));

    while (true) {
        if (tid == 0) s_tile = (int)atomicAdd(&g_tile_ctr, 1u);
        __syncthreads();
        const int tile = s_tile;
        if (tile >= NTILES) break;
        const int row0 = tile * 128;

        LOAD_CHUNK(0, 0);   // overlap first B chunk with A prologue

        if (tid < 128) {
            x2s[tid] = g_x2[row0 + tid];
            rmin[tid] = 0xFFFFFFFFu;
            scnt[tid] = 0;
            red[tid] = ~0ull;
        }

        // ---- A prologue: x rows -> bf16 fragment layout in smem ----
        {
            const int d0 = (tid & 127) << 1;
            const int rsel = tid >> 7;
            const int kbg = d0 >> 4;
            const int ln  = (d0 & 7) >> 1;
            const int kh  = (d0 >> 3) & 1;
            #pragma unroll 4
            for (int i = 0; i < 64; i++) {
                int row = (i << 1) | rsel;
                float2 v = *reinterpret_cast<const float2*>(
                    x + (size_t)(row0 + row) * DIM + d0);
                uint32_t p = bfpack(v.x, v.y);
                int mb = row >> 4;
                int lfull = ((row & 7) << 2) | ln;
                int reg = ((row >> 3) & 1) | (kh << 1);
                As[((mb * 16 + kbg) << 7) + (lfull << 2) + reg] = p;
            }
        }
        __syncthreads();

        float acc[4][4][4];

        for (int kt = 0; kt < 32; kt++) {
            #pragma unroll
            for (int rb = 0; rb < 4; rb++)
                #pragma unroll
                for (int nb = 0; nb < 4; nb++)
                    #pragma unroll
                    for (int cc = 0; cc < 4; cc++) acc[rb][nb][cc] = 0.f;

            for (int dc = 0; dc < 4; dc++) {
                int ic = kt * 4 + dc;
                if (ic + 1 < 128) {
                    LOAD_CHUNK(ic + 1, (ic + 1) & 1);
                    asm volatile("cp.async.wait_group 1;" ::: "memory");
                } else {
                    asm volatile("cp.async.wait_group 0;" ::: "memory");
                }
                __syncthreads();
                const uint32_t* B = Bs + (ic & 1) * 4096;

                #pragma unroll
                for (int kb = 0; kb < 4; kb++) {
                    int kbg = dc * 4 + kb;
                    uint4 A4[4];
                    uint2 B2[4];
                    #pragma unroll
                    for (int rb = 0; rb < 4; rb++)
                        A4[rb] = *reinterpret_cast<const uint4*>(
                            As + (((wr * 4 + rb) * 16 + kbg) << 7) + (lane << 2));
                    #pragma unroll
                    for (int nb = 0; nb < 4; nb++)
                        B2[nb] = *reinterpret_cast<const uint2*>(
                            B + ((kb * 16 + wc * 4 + nb) * 32 + lane) * 2);
                    #pragma unroll
                    for (int rb = 0; rb < 4; rb++)
                        #pragma unroll
                        for (int nb = 0; nb < 4; nb++)
                            MMA16(acc[rb][nb], A4[rb], B2[nb]);
                }
                __syncthreads();
            }

            // ---- epilogue: dist, shfl-reduced row-min, candidates ----
            float e2v[4][2];
            #pragma unroll
            for (int nb = 0; nb < 4; nb++) {
                int c0 = kt * 128 + wc * 32 + nb * 8 + tig * 2;
                e2v[nb][0] = g_e2[c0];
                e2v[nb][1] = g_e2[c0 + 1];
            }
            #pragma unroll
            for (int rb = 0; rb < 4; rb++) {
                #pragma unroll
                for (int h = 0; h < 2; h++) {
                    int r = wr * 64 + rb * 16 + gg + h * 8;
                    float m = 3.4e38f;
                    #pragma unroll
                    for (int nb = 0; nb < 4; nb++)
                        #pragma unroll
                        for (int w = 0; w < 2; w++) {
                            int cc = h * 2 + w;
                            float dist = (x2s[r] + e2v[nb][w]) - 2.0f * acc[rb][nb][cc];
                            acc[rb][nb][cc] = dist;
                            m = fminf(m, dist);
                        }
                    m = fminf(m, __shfl_xor_sync(0xffffffffu, m, 1));
                    m = fminf(m, __shfl_xor_sync(0xffffffffu, m, 2));
                    if (tig == 0) atomicMin(&rmin[r], fenc(m));
                }
            }
            __syncthreads();
            #pragma unroll
            for (int rb = 0; rb < 4; rb++)
                #pragma unroll
                for (int h = 0; h < 2; h++) {
                    int r = wr * 64 + rb * 16 + gg + h * 8;
                    float thr = fdec(rmin[r]) + TH;
                    #pragma unroll
                    for (int nb = 0; nb < 4; nb++)
                        #pragma unroll
                        for (int w = 0; w < 2; w++) {
                            if (acc[rb][nb][h * 2 + w] < thr) {
                                int s = atomicAdd(&scnt[r], 1);
                                if (s < CAND_MAX) {
                                    int code = kt * 128 + wc * 32 + nb * 8 + tig * 2 + w;
                                    cand[r * CAND_MAX + s] = (unsigned short)code;
                                }
                            }
                        }
                }
        }

        // ---- exact fp32 rescore ----
        __syncthreads();
        for (int t2 = 0; t2 < 16; t2++) {
            int r = warp * 16 + t2;
            int c = scnt[r];
            if (c > CAND_MAX) {
                if (lane == 0) {
                    int fi = atomicAdd(&g_fb_count, 1);
                    g_fb_rows[fi] = row0 + r;
                }
                continue;
            }
            #pragma unroll
            for (int base = 0; base < CAND_MAX; base += 32) {
                int li = base + lane;
                if (li < c) {
                    int idx = cand[r * CAND_MAX + li];
                    float dist = exact_dist(x + (size_t)(row0 + r) * DIM,
                                            cb + (size_t)idx * DIM, x2s[r], g_e2[idx]);
                    unsigned long long key =
                        ((unsigned long long)fenc(dist) << 32) | (unsigned)idx;
                    atomicMin(&red[r], key);
                }
            }
        }
        __syncthreads();
        if (tid < 128 && scnt[tid] <= CAND_MAX)
            g_idx[row0 + tid] = (int)(red[tid] & 0xFFFFFFFFu);
        __syncthreads();   // protect smem statics before next tile
    }
}

// ---------------------------------------------------------------------------
// Fallback: exact full scan for overflowed rows (parallel: 512 blocks).
// ---------------------------------------------------------------------------
__global__ void fb_kernel(const float* __restrict__ x, const float* __restrict__ cb) {
    __shared__ unsigned long long rr;
    int n = g_fb_count;
    for (int fi = blockIdx.x; fi < n; fi += gridDim.x) {
        int row = g_fb_rows[fi];
        if (threadIdx.x == 0) rr = ~0ull;
        __syncthreads();
        float x2 = g_x2[row];
        for (int c = threadIdx.x; c < KCB; c += blockDim.x) {
            float dist = exact_dist(x + (size_t)row * DIM, cb + (size_t)c * DIM,
                                    x2, g_e2[c]);
            unsigned long long key =
                ((unsigned long long)fenc(dist) << 32) | (unsigned)c;
            atomicMin(&rr, key);
        }
        __syncthreads();
        if (threadIdx.x == 0) g_idx[row] = (int)(rr & 0xFFFFFFFFu);
        __syncthreads();
    }
}

// ---------------------------------------------------------------------------
__global__ void vq_output_kernel(const float* __restrict__ x,
                                 const float* __restrict__ cb,
                                 float* __restrict__ out) {
    __shared__ double sred[256];
    double lsum = 0.0;
    const int nthreads = gridDim.x * blockDim.x;
    const int total4 = NVEC * DIM / 4;
    const float4* x4 = reinterpret_cast<const float4*>(x);
    float4* o4 = reinterpret_cast<float4*>(out);

    for (int i = blockIdx.x * blockDim.x + threadIdx.x; i < total4; i += nthreads) {
        int n = i >> 6;
        int idx = g_idx[n];
        float4 q  = reinterpret_cast<const float4*>(cb + (size_t)idx * DIM)[i & 63];
        float4 xv = x4[i];
        float4 r;
        float d0 = q.x - xv.x; r.x = xv.x + d0; lsum += (double)(d0 * d0);
        float d1 = q.y - xv.y; r.y = xv.y + d1; lsum += (double)(d1 * d1);
        float d2 = q.z - xv.z; r.z = xv.z + d2; lsum += (double)(d2 * d2);
        float d3 = q.w - xv.w; r.w = xv.w + d3; lsum += (double)(d3 * d3);
        o4[i] = r;
    }
    sred[threadIdx.x] = lsum;
    __syncthreads();
    #pragma unroll
    for (int s = 128; s; s >>= 1) {
        if (threadIdx.x < s) sred[threadIdx.x] += sred[threadIdx.x + s];
        __syncthreads();
    }
    if (threadIdx.x == 0) g_part[blockIdx.x] = sred[0];
}

__global__ void loss_kernel(float* __restrict__ out, int out_size) {
    __shared__ double sred[256];
    double s = 0.0;
    for (int i = threadIdx.x; i < LOSS_BLOCKS; i += 256) s += g_part[i];
    sred[threadIdx.x] = s;
    __syncthreads();
    #pragma unroll
    for (int k = 128; k; k >>= 1) {
        if (threadIdx.x < k) sred[threadIdx.x] += sred[threadIdx.x + k];
        __syncthreads();
    }
    const int nq = NVEC * DIM;
    if (threadIdx.x == 0) {
        double m = sred[0] / (double)nq;
        float mf = (float)m;
        float loss = mf + 0.25f * mf;
        if (out_size == nq + 1)      out[nq] = loss;
        else if (out_size == 1)      out[0] = loss;
        else if (out_size > nq)      out[out_size - 1] = loss;
    }
    for (int i = nq + 1 + threadIdx.x; i < out_size - 1; i += 256) out[i] = 0.f;
}

// ---------------------------------------------------------------------------
extern "C" void kernel_launch(void* const* d_in, const int* in_sizes, int n_in,
                              void* d_out, int out_size) {
    const float* x  = (const float*)d_in[0];
    const float* cb = (const float*)d_in[1];
    if (n_in >= 2 && in_sizes[0] == KCB * DIM && in_sizes[1] == NVEC * DIM) {
        const float* t = x; x = cb; cb = t;
    }
    float* out = (float*)d_out;

    cudaFuncSetAttribute(vq_mma_kernel,
                         cudaFuncAttributeMaxDynamicSharedMemorySize, 98304);

    bperm_kernel<<<KCB * DIM / 2 / 256, 256>>>(cb);
    rownorm_kernel<<<NVEC / 8, 256>>>(x,  NVEC, 0);
    rownorm_kernel<<<KCB  / 8, 256>>>(cb, KCB,  1);
    vq_mma_kernel<<<GRID_MMA, 256, 98304>>>(x, cb);
    fb_kernel<<<512, 256>>>(x, cb);
    vq_output_kernel<<<LOSS_BLOCKS, 256>>>(x, cb, out);
    loss_kernel<<<1, 256>>>(out, out_size);
}

// round 11
// speedup vs baseline: 1.0718x; 1.0718x over previous
#include <cuda_runtime.h>
#include <cstdint>

#define NVEC 65536
#define DIM  256
#define KCB  4096
#define LOSS_BLOCKS 4096
#define CAND_MAX 40
#define TH 1.0e-3f
#define TROWS 64                 // rows per CTA tile
#define NTILES (NVEC / TROWS)    // 1024

__device__ float    g_x2[NVEC];
__device__ float    g_e2[KCB];
__device__ int      g_idx[NVEC];
__device__ double   g_part[LOSS_BLOCKS];
__device__ uint32_t g_bperm[KCB * DIM / 2];   // bf16x2 fragment-permuted codebook
__device__ int      g_fb_rows[NVEC];
__device__ int      g_fb_count;

__device__ __forceinline__ unsigned fenc(float f) {
    unsigned u = __float_as_uint(f);
    return (u & 0x80000000u) ? ~u : (u | 0x80000000u);
}
__device__ __forceinline__ float fdec(unsigned e) {
    unsigned u = (e & 0x80000000u) ? (e ^ 0x80000000u) : ~e;
    return __uint_as_float(u);
}
// pack bf16x2: lo half = v0, hi half = v1
__device__ __forceinline__ uint32_t bfpack(float v0, float v1) {
    uint32_t r;
    asm("cvt.rn.bf16x2.f32 %0, %1, %2;" : "=r"(r) : "f"(v1), "f"(v0));
    return r;
}

// Exact fp32 distance — identical recipe to rounds 1/4/5/7 (rel_err 0.0)
__device__ __forceinline__ float exact_dist(const float* __restrict__ xr,
                                            const float* __restrict__ cr,
                                            float x2, float e2) {
    const float4* x4 = reinterpret_cast<const float4*>(xr);
    const float4* c4 = reinterpret_cast<const float4*>(cr);
    float acc = 0.f;
    #pragma unroll 8
    for (int q = 0; q < 64; q++) {
        float4 a = x4[q], b = c4[q];
        acc = fmaf(a.x, b.x, acc);
        acc = fmaf(a.y, b.y, acc);
        acc = fmaf(a.z, b.z, acc);
        acc = fmaf(a.w, b.w, acc);
    }
    float t = x2 + e2;
    return t - 2.0f * acc;
}

// ---------------------------------------------------------------------------
__global__ void rownorm_kernel(const float* __restrict__ v, int rows, int which) {
    if (which == 0 && blockIdx.x == 0 && threadIdx.x == 0) g_fb_count = 0;
    int row  = blockIdx.x * (blockDim.x >> 5) + (threadIdx.x >> 5);
    int lane = threadIdx.x & 31;
    if (row >= rows) return;
    const float4* p = reinterpret_cast<const float4*>(v + (size_t)row * DIM);
    float4 a = p[lane];
    float4 b = p[lane + 32];
    float s = ((a.x * a.x + a.y * a.y) + (a.z * a.z + a.w * a.w))
            + ((b.x * b.x + b.y * b.y) + (b.z * b.z + b.w * b.w));
    #pragma unroll
    for (int off = 16; off; off >>= 1)
        s += __shfl_xor_sync(0xffffffffu, s, off);
    if (lane == 0) {
        if (which) g_e2[row] = s;
        else       g_x2[row] = s;
    }
}

// ---------------------------------------------------------------------------
// Pre-convert codebook to bf16 in mma.m16n8k16 B-fragment layout (as R7/R9).
// Layout: [chunk 128][kb 4][nb 16][lane 32][reg 2] (u32 = bf16x2)
// ---------------------------------------------------------------------------
__global__ void bperm_kernel(const float* __restrict__ cb) {
    int o = blockIdx.x * 256 + threadIdx.x;    // total 524288
    int reg = o & 1, lane = (o >> 1) & 31, nb = (o >> 6) & 15, kb = (o >> 10) & 3;
    int chunk = o >> 12, kt = chunk >> 2, dc = chunk & 3;
    int gg = lane >> 2, tig = lane & 3;
    int code = kt * 128 + nb * 8 + gg;
    int d0 = dc * 64 + kb * 16 + 2 * tig + reg * 8;
    const float* r = cb + (size_t)code * DIM;
    g_bperm[o] = bfpack(r[d0], r[d0 + 1]);
}

// ---------------------------------------------------------------------------
// bf16 mma.sync distance GEMM + candidate collection + exact fp32 rescore.
// CTA tile: 64 rows x 4096 codes (3 CTAs/SM for 24 warps of latency hiding).
// 8 warps (2 wr x 4 wc); warp tile 32 rows x 32 codes.
// ---------------------------------------------------------------------------
#define MMA16(ac, av, bv) \
    asm volatile("mma.sync.aligned.m16n8k16.row.col.f32.bf16.bf16.f32 " \
        "{%0,%1,%2,%3},{%4,%5,%6,%7},{%8,%9},{%0,%1,%2,%3};" \
        : "+f"((ac)[0]), "+f"((ac)[1]), "+f"((ac)[2]), "+f"((ac)[3]) \
        : "r"((av).x), "r"((av).y), "r"((av).z), "r"((av).w), \
          "r"((bv).x), "r"((bv).y))

// chunk = 16KB: 256 threads x 16B x 4
#define LOAD_CHUNK(c, buf) do {                                               \
    const uint32_t* _src = g_bperm + (size_t)(c) * 4096 + tid * 4;            \
    uint32_t _dst = bsb + (uint32_t)(buf) * 16384u + (uint32_t)tid * 16u;     \
    _Pragma("unroll")                                                         \
    for (int _j = 0; _j < 4; _j++)                                            \
        asm volatile("cp.async.cg.shared.global [%0], [%1], 16;"              \
                     :: "r"(_dst + _j * 4096u), "l"(_src + _j * 1024) : "memory"); \
    asm volatile("cp.async.commit_group;" ::: "memory");                      \
} while (0)

__global__ __launch_bounds__(256, 3)
void vq_mma_kernel(const float* __restrict__ x, const float* __restrict__ cb) {
    extern __shared__ uint32_t dsm[];
    uint32_t* As = dsm;            // 8192 u32 = 32KB (A bf16 fragments, 64 rows)
    uint32_t* Bs = dsm + 8192;     // 8192 u32 = 32KB (2 x 16KB B chunks)
    __shared__ float x2s[TROWS];
    __shared__ unsigned rmin[TROWS];
    __shared__ int scnt[TROWS];
    __shared__ unsigned short cand[TROWS * CAND_MAX];
    __shared__ unsigned long long red[TROWS];

    const int tid = threadIdx.x, lane = tid & 31, warp = tid >> 5;
    const int wr = warp >> 2, wc = warp & 3;
    const int gg = lane >> 2, tig = lane & 3;
    const int row0 = blockIdx.x * TROWS;

    uint32_t bsb;
    asm("{ .reg .u64 t; cvta.to.shared.u64 t, %1; cvt.u32.u64 %0, t; }"
        : "=r"(bsb) : "l"(Bs));

    LOAD_CHUNK(0, 0);   // overlap first B chunk with A prologue

    if (tid < TROWS) {
        x2s[tid] = g_x2[row0 + tid];
        rmin[tid] = 0xFFFFFFFFu;
        scnt[tid] = 0;
        red[tid] = ~0ull;
    }

    // ---- A prologue: 64 x rows -> bf16 fragment layout in smem ----
    // thread = (row = tid>>2, 32 d-pairs starting at (tid&3)*32)
    {
        const int row = tid >> 2;
        const int p0 = (tid & 3) << 5;
        const int mb = row >> 4;
        const int lrow = (row & 7) << 2;
        const int hi = (row >> 3) & 1;
        const float2* xr2 = reinterpret_cast<const float2*>(
            x + (size_t)(row0 + row) * DIM);
        #pragma unroll 8
        for (int i = 0; i < 32; i++) {
            int p = p0 + i;              // d-pair index, d0 = 2p
            float2 v = xr2[p];
            uint32_t pk = bfpack(v.x, v.y);
            int d0 = p << 1;
            int kbg = d0 >> 4;
            int lfull = lrow | ((d0 & 7) >> 1);
            int reg = hi | (((d0 >> 3) & 1) << 1);
            As[((mb * 16 + kbg) << 7) + (lfull << 2) + reg] = pk;
        }
    }
    __syncthreads();

    float acc[2][4][4];

    for (int kt = 0; kt < 32; kt++) {
        #pragma unroll
        for (int rb = 0; rb < 2; rb++)
            #pragma unroll
            for (int nb = 0; nb < 4; nb++)
                #pragma unroll
                for (int cc = 0; cc < 4; cc++) acc[rb][nb][cc] = 0.f;

        for (int dc = 0; dc < 4; dc++) {
            int ic = kt * 4 + dc;
            if (ic + 1 < 128) {
                LOAD_CHUNK(ic + 1, (ic + 1) & 1);
                asm volatile("cp.async.wait_group 1;" ::: "memory");
            } else {
                asm volatile("cp.async.wait_group 0;" ::: "memory");
            }
            __syncthreads();
            const uint32_t* B = Bs + (ic & 1) * 4096;

            #pragma unroll
            for (int kb = 0; kb < 4; kb++) {
                int kbg = dc * 4 + kb;
                uint4 A4[2];
                uint2 B2[4];
                #pragma unroll
                for (int rb = 0; rb < 2; rb++)
                    A4[rb] = *reinterpret_cast<const uint4*>(
                        As + (((wr * 2 + rb) * 16 + kbg) << 7) + (lane << 2));
                #pragma unroll
                for (int nb = 0; nb < 4; nb++)
                    B2[nb] = *reinterpret_cast<const uint2*>(
                        B + ((kb * 16 + wc * 4 + nb) * 32 + lane) * 2);
                #pragma unroll
                for (int rb = 0; rb < 2; rb++)
                    #pragma unroll
                    for (int nb = 0; nb < 4; nb++)
                        MMA16(acc[rb][nb], A4[rb], B2[nb]);
            }
            __syncthreads();
        }

        // ---- epilogue: dist, shfl-reduced row-min, candidates ----
        float e2v[4][2];
        #pragma unroll
        for (int nb = 0; nb < 4; nb++) {
            int c0 = kt * 128 + wc * 32 + nb * 8 + tig * 2;
            e2v[nb][0] = g_e2[c0];
            e2v[nb][1] = g_e2[c0 + 1];
        }
        #pragma unroll
        for (int rb = 0; rb < 2; rb++) {
            #pragma unroll
            for (int h = 0; h < 2; h++) {
                int r = wr * 32 + rb * 16 + gg + h * 8;
                float m = 3.4e38f;
                #pragma unroll
                for (int nb = 0; nb < 4; nb++)
                    #pragma unroll
                    for (int w = 0; w < 2; w++) {
                        int cc = h * 2 + w;
                        float dist = (x2s[r] + e2v[nb][w]) - 2.0f * acc[rb][nb][cc];
                        acc[rb][nb][cc] = dist;
                        m = fminf(m, dist);
                    }
                m = fminf(m, __shfl_xor_sync(0xffffffffu, m, 1));
                m = fminf(m, __shfl_xor_sync(0xffffffffu, m, 2));
                if (tig == 0) atomicMin(&rmin[r], fenc(m));
            }
        }
        __syncthreads();
        #pragma unroll
        for (int rb = 0; rb < 2; rb++)
            #pragma unroll
            for (int h = 0; h < 2; h++) {
                int r = wr * 32 + rb * 16 + gg + h * 8;
                float thr = fdec(rmin[r]) + TH;
                #pragma unroll
                for (int nb = 0; nb < 4; nb++)
                    #pragma unroll
                    for (int w = 0; w < 2; w++) {
                        if (acc[rb][nb][h * 2 + w] < thr) {
                            int s = atomicAdd(&scnt[r], 1);
                            if (s < CAND_MAX) {
                                int code = kt * 128 + wc * 32 + nb * 8 + tig * 2 + w;
                                cand[r * CAND_MAX + s] = (unsigned short)code;
                            }
                        }
                    }
            }
    }

    // ---- exact fp32 rescore ----
    __syncthreads();
    for (int t2 = 0; t2 < TROWS / 8; t2++) {
        int r = warp * (TROWS / 8) + t2;
        int c = scnt[r];
        if (c > CAND_MAX) {
            if (lane == 0) {
                int fi = atomicAdd(&g_fb_count, 1);
                g_fb_rows[fi] = row0 + r;
            }
            continue;
        }
        #pragma unroll
        for (int base = 0; base < CAND_MAX; base += 32) {
            int li = base + lane;
            if (li < c) {
                int idx = cand[r * CAND_MAX + li];
                float dist = exact_dist(x + (size_t)(row0 + r) * DIM,
                                        cb + (size_t)idx * DIM, x2s[r], g_e2[idx]);
                unsigned long long key =
                    ((unsigned long long)fenc(dist) << 32) | (unsigned)idx;
                atomicMin(&red[r], key);
            }
        }
    }
    __syncthreads();
    if (tid < TROWS && scnt[tid] <= CAND_MAX)
        g_idx[row0 + tid] = (int)(red[tid] & 0xFFFFFFFFu);
}

// ---------------------------------------------------------------------------
// Fallback: exact full scan for overflowed rows (parallel: 512 blocks).
// ---------------------------------------------------------------------------
__global__ void fb_kernel(const float* __restrict__ x, const float* __restrict__ cb) {
    __shared__ unsigned long long rr;
    int n = g_fb_count;
    for (int fi = blockIdx.x; fi < n; fi += gridDim.x) {
        int row = g_fb_rows[fi];
        if (threadIdx.x == 0) rr = ~0ull;
        __syncthreads();
        float x2 = g_x2[row];
        for (int c = threadIdx.x; c < KCB; c += blockDim.x) {
            float dist = exact_dist(x + (size_t)row * DIM, cb + (size_t)c * DIM,
                                    x2, g_e2[c]);
            unsigned long long key =
                ((unsigned long long)fenc(dist) << 32) | (unsigned)c;
            atomicMin(&rr, key);
        }
        __syncthreads();
        if (threadIdx.x == 0) g_idx[row] = (int)(rr & 0xFFFFFFFFu);
        __syncthreads();
    }
}

// ---------------------------------------------------------------------------
__global__ void vq_output_kernel(const float* __restrict__ x,
                                 const float* __restrict__ cb,
                                 float* __restrict__ out) {
    __shared__ double sred[256];
    double lsum = 0.0;
    const int nthreads = gridDim.x * blockDim.x;
    const int total4 = NVEC * DIM / 4;
    const float4* x4 = reinterpret_cast<const float4*>(x);
    float4* o4 = reinterpret_cast<float4*>(out);

    for (int i = blockIdx.x * blockDim.x + threadIdx.x; i < total4; i += nthreads) {
        int n = i >> 6;
        int idx = g_idx[n];
        float4 q  = reinterpret_cast<const float4*>(cb + (size_t)idx * DIM)[i & 63];
        float4 xv = x4[i];
        float4 r;
        float d0 = q.x - xv.x; r.x = xv.x + d0; lsum += (double)(d0 * d0);
        float d1 = q.y - xv.y; r.y = xv.y + d1; lsum += (double)(d1 * d1);
        float d2 = q.z - xv.z; r.z = xv.z + d2; lsum += (double)(d2 * d2);
        float d3 = q.w - xv.w; r.w = xv.w + d3; lsum += (double)(d3 * d3);
        o4[i] = r;
    }
    sred[threadIdx.x] = lsum;
    __syncthreads();
    #pragma unroll
    for (int s = 128; s; s >>= 1) {
        if (threadIdx.x < s) sred[threadIdx.x] += sred[threadIdx.x + s];
        __syncthreads();
    }
    if (threadIdx.x == 0) g_part[blockIdx.x] = sred[0];
}

__global__ void loss_kernel(float* __restrict__ out, int out_size) {
    __shared__ double sred[256];
    double s = 0.0;
    for (int i = threadIdx.x; i < LOSS_BLOCKS; i += 256) s += g_part[i];
    sred[threadIdx.x] = s;
    __syncthreads();
    #pragma unroll
    for (int k = 128; k; k >>= 1) {
        if (threadIdx.x < k) sred[threadIdx.x] += sred[threadIdx.x + k];
        __syncthreads();
    }
    const int nq = NVEC * DIM;
    if (threadIdx.x == 0) {
        double m = sred[0] / (double)nq;
        float mf = (float)m;
        float loss = mf + 0.25f * mf;
        if (out_size == nq + 1)      out[nq] = loss;
        else if (out_size == 1)      out[0] = loss;
        else if (out_size > nq)      out[out_size - 1] = loss;
    }
    for (int i = nq + 1 + threadIdx.x; i < out_size - 1; i += 256) out[i] = 0.f;
}

// ---------------------------------------------------------------------------
extern "C" void kernel_launch(void* const* d_in, const int* in_sizes, int n_in,
                              void* d_out, int out_size) {
    const float* x  = (const float*)d_in[0];
    const float* cb = (const float*)d_in[1];
    if (n_in >= 2 && in_sizes[0] == KCB * DIM && in_sizes[1] == NVEC * DIM) {
        const float* t = x; x = cb; cb = t;
    }
    float* out = (float*)d_out;

    cudaFuncSetAttribute(vq_mma_kernel,
                         cudaFuncAttributeMaxDynamicSharedMemorySize, 65536);

    bperm_kernel<<<KCB * DIM / 2 / 256, 256>>>(cb);
    rownorm_kernel<<<NVEC / 8, 256>>>(x,  NVEC, 0);
    rownorm_kernel<<<KCB  / 8, 256>>>(cb, KCB,  1);
    vq_mma_kernel<<<NTILES, 256, 65536>>>(x, cb);
    fb_kernel<<<512, 256>>>(x, cb);
    vq_output_kernel<<<LOSS_BLOCKS, 256>>>(x, cb, out);
    loss_kernel<<<1, 256>>>(out, out_size);
}